// round 11
// baseline (speedup 1.0000x reference)
#include <cuda_runtime.h>
#include <cuda_fp16.h>
#include <math.h>

#define BATCH 8
#define CH 64
#define PLANE 50176            /* 224*224 */
#define NTPB 1568              /* 32px tiles per batch */
#define POOLED_ELEMS 4194304

// ---------------- device scratch ----------------
__device__ __half g_xTh[(size_t)BATCH*PLANE*CH];  // [B][pix][C] fp16
__device__ float  g_part[(size_t)BATCH*NTPB*CH];  // per-tile channel partials
__device__ float  g_lohi[16];
__device__ float  g_cval[BATCH*CH];
__device__ float2 g_polar[8192];                  // (logr, a/pi - 1)

// ---- transpose 2 batches: 32px tiles, fp16 channel-packed + partials ----
__global__ void __launch_bounds__(256) k_T(const float* __restrict__ x, int b0) {
    __shared__ float tile[CH][33];
    int bx   = blockIdx.x;
    int b    = b0 + bx / NTPB;
    int tidx = bx % NTPB;
    int t0   = tidx * 32;
    int tid  = threadIdx.x;

    const float4* xp = (const float4*)(x + (size_t)b * CH * PLANE);
    int base4 = t0 >> 2;
#pragma unroll
    for (int it = 0; it < 2; it++) {
        int p    = it * 256 + tid;
        int c    = p >> 3;
        int col4 = p & 7;
        float4 v = xp[(size_t)c * (PLANE / 4) + base4 + col4];
        tile[c][col4*4+0] = v.x; tile[c][col4*4+1] = v.y;
        tile[c][col4*4+2] = v.z; tile[c][col4*4+3] = v.w;
    }
    __syncthreads();

    if (tid < CH) {
        float s = 0.f;
#pragma unroll
        for (int k = 0; k < 32; k++) s += tile[tid][k];
        g_part[((size_t)b * NTPB + tidx) * CH + tid] = s;
    }

    int rr = tid >> 3, q = tid & 7;
    half2 h0 = __floats2half2_rn(tile[8*q+0][rr], tile[8*q+1][rr]);
    half2 h1 = __floats2half2_rn(tile[8*q+2][rr], tile[8*q+3][rr]);
    half2 h2 = __floats2half2_rn(tile[8*q+4][rr], tile[8*q+5][rr]);
    half2 h3 = __floats2half2_rn(tile[8*q+6][rr], tile[8*q+7][rr]);
    uint4 u;
    u.x = *(unsigned int*)&h0; u.y = *(unsigned int*)&h1;
    u.z = *(unsigned int*)&h2; u.w = *(unsigned int*)&h3;
    ((uint4*)g_xTh)[((size_t)b * PLANE + t0 + rr) * 8 + q] = u;
}

// ---- small: polar table + constant-region bilinear values ---------------
__global__ void __launch_bounds__(256) k_small(const float* __restrict__ x,
                                               const float* __restrict__ l) {
    int tid = threadIdx.x;
    for (int e = tid; e < 8192; e += 256) {
        int i = e >> 7, j = e & 127;
        float xg = (i - 32) * (1.f / 32.f);
        float yg = (j - 64) * (1.f / 64.f);
        float logr = logf(fmaxf(sqrtf(xg*xg + yg*yg), 1e-12f));
        float a = atan2f(yg, xg);
        if (!(a > 0.f)) a += 6.283185307179586f;
        g_polar[e] = make_float2(logr, a * 0.3183098861837907f - 1.f);
    }
#pragma unroll
    for (int rep = 0; rep < 2; rep++) {
        int idx = rep * 256 + tid;
        int b = idx >> 6;
        float gx = l[2*b], gy = l[2*b + 1];
        float ix = fminf(fmaxf((gx + 1.f) * 112.f - 0.5f, 0.f), 223.f);
        float iy = fminf(fmaxf((gy + 1.f) * 112.f - 0.5f, 0.f), 223.f);
        float x0f = floorf(ix), y0f = floorf(iy);
        float wx = ix - x0f, wy = iy - y0f;
        int x0 = (int)x0f, y0 = (int)y0f;
        int x1 = min(x0 + 1, 223), y1 = min(y0 + 1, 223);
        const float* pp = x + (size_t)idx * PLANE;
        g_cval[idx] = pp[y0*224 + x0] * (1.f-wx) * (1.f-wy)
                    + pp[y0*224 + x1] * wx * (1.f-wy)
                    + pp[y1*224 + x0] * (1.f-wx) * wy
                    + pp[y1*224 + x1] * wx * wy;
    }
}

// ---- fill: outer constant region for all 8 batches ----------------------
__global__ void __launch_bounds__(256) k_fill(float* __restrict__ out) {
    int idx = blockIdx.x * 256 + threadIdx.x;   // float4 index
    int plane = idx >> 11;
    int rem = idx & 2047;
    int h = rem >> 5, w4 = rem & 31;
    if (h < 16 && w4 < 8) return;
    float v = g_cval[plane];
    __stcs(&((float4*)out)[idx], make_float4(v, v, v, v));
}

// ---- red+MLP for 2 batches: float4, deep-MLP reduce, then fc ------------
__global__ void __launch_bounds__(1024) k_red(
        const float* __restrict__ w1, const float* __restrict__ b1,
        const float* __restrict__ w2, const float* __restrict__ b2,
        float* __restrict__ outw, int b0) {
    __shared__ float4 red4[49][16];
    __shared__ float br[CH];
    __shared__ float hid[32];
    __shared__ float wgt[2];
    int b = b0 + blockIdx.x;
    int tid = threadIdx.x;
    int c4 = tid & 15, grp = tid >> 4;        // 64 groups x 16 quads

    if (grp < 49) {                           // 49 groups x 32 tiles = 1568
        const float4* p4 = (const float4*)g_part;
        size_t base = ((size_t)b * NTPB + grp * 32) * 16 + c4;
        float4 a = make_float4(0.f, 0.f, 0.f, 0.f);
#pragma unroll
        for (int t = 0; t < 32; t++) {        // 32 independent float4 loads
            float4 v = p4[base + (size_t)t * 16];
            a.x += v.x; a.y += v.y; a.z += v.z; a.w += v.w;
        }
        red4[grp][c4] = a;
    }
    __syncthreads();

    if (tid < 16) {                           // sum 49 groups per quad
        float4 s = make_float4(0.f, 0.f, 0.f, 0.f);
#pragma unroll
        for (int g = 0; g < 49; g++) {
            float4 v = red4[g][tid];
            s.x += v.x; s.y += v.y; s.z += v.z; s.w += v.w;
        }
        const float inv = 1.f / (float)PLANE;
        br[4*tid+0] = s.x * inv; br[4*tid+1] = s.y * inv;
        br[4*tid+2] = s.z * inv; br[4*tid+3] = s.w * inv;
    }
    __syncthreads();

    if (tid < 32) {
        float acc = b1[tid];
#pragma unroll
        for (int cc = 0; cc < 64; cc++) acc += br[cc] * w1[cc * 32 + tid];
        hid[tid] = fmaxf(acc, 0.f);
    }
    __syncthreads();
    if (tid < 2) {
        float acc = b2[tid];
#pragma unroll
        for (int m = 0; m < 32; m++) acc += hid[m] * w2[m * 2 + tid];
        float wv = 1.f / (1.f + expf(-acc));
        wgt[tid] = wv;
        outw[2 * b + tid] = wv;
    }
    __syncthreads();
    if (tid == 0) {
        g_lohi[2*b + 0] = logf(wgt[0] * 0.01f);
        g_lohi[2*b + 1] = logf(wgt[1] * 0.60f);
    }
}

// ---- gather 2 batches: inner region, channel-packed fp16 taps -----------
__global__ void __launch_bounds__(256) k_g(const float* __restrict__ l,
                                           float* __restrict__ out, int b0) {
    __shared__ float st[8][68];
    int warpId = threadIdx.x >> 5;
    int lane   = threadIdx.x & 31;
    int wpos   = blockIdx.x * 8 + warpId;   // 0..1023
    int b   = b0 + (wpos >> 9);
    int pos = wpos & 511;
    int h = pos >> 5, w = pos & 31;
    int tap = lane >> 3, c8 = lane & 7;

    float l0 = l[2*b], l1 = l[2*b + 1];
    float lo = g_lohi[2*b], hi = g_lohi[2*b + 1];
    float inv2 = 2.f / (hi - lo);

    int s16 = lane & 15;
    int i = 4 * h + (s16 >> 2);
    int j = 4 * w + (s16 & 3);
    float2 pb = g_polar[(i << 7) | j];
    float gx = pb.y + l0;
    float gy = (pb.x - lo) * inv2 - 1.f + l1;
    float ix = fminf(fmaxf((gx + 1.f) * 112.f - 0.5f, 0.f), 223.f);
    float iy = fminf(fmaxf((gy + 1.f) * 112.f - 0.5f, 0.f), 223.f);

    const uint4* xt = (const uint4*)g_xTh;
    size_t bbase = (size_t)b * PLANE * 8;
    float acc[8];
#pragma unroll
    for (int k = 0; k < 8; k++) acc[k] = 0.f;

#pragma unroll
    for (int s = 0; s < 16; s++) {
        float ixs = __shfl_sync(0xffffffffu, ix, s);
        float iys = __shfl_sync(0xffffffffu, iy, s);
        float x0f = floorf(ixs), y0f = floorf(iys);
        float wx = ixs - x0f, wy = iys - y0f;
        int x0 = (int)x0f, y0 = (int)y0f;
        int x1 = min(x0 + 1, 223), y1 = min(y0 + 1, 223);
        int xs = (tap & 1) ? x1 : x0;
        int ys = (tap & 2) ? y1 : y0;
        float wt = ((tap & 1) ? wx : 1.f - wx) * ((tap & 2) ? wy : 1.f - wy);
        uint4 v = xt[bbase + (size_t)(ys * 224 + xs) * 8 + c8];
        half2* hp = (half2*)&v;
        float2 f0 = __half22float2(hp[0]);
        float2 f1 = __half22float2(hp[1]);
        float2 f2 = __half22float2(hp[2]);
        float2 f3 = __half22float2(hp[3]);
        acc[0] += wt * f0.x;  acc[1] += wt * f0.y;
        acc[2] += wt * f1.x;  acc[3] += wt * f1.y;
        acc[4] += wt * f2.x;  acc[5] += wt * f2.y;
        acc[6] += wt * f3.x;  acc[7] += wt * f3.y;
    }
#pragma unroll
    for (int k = 0; k < 8; k++) {
        acc[k] += __shfl_xor_sync(0xffffffffu, acc[k], 8);
        acc[k] += __shfl_xor_sync(0xffffffffu, acc[k], 16);
    }
    if (tap == 0) {
#pragma unroll
        for (int k = 0; k < 8; k++)
            st[warpId][8 * c8 + k] = acc[k] * (1.f / 16.f);
    }
    __syncthreads();

    if (threadIdx.x < 64) {
        int c = threadIdx.x;
        int p0 = (blockIdx.x * 8) & 511;
        int hB = p0 >> 5, w0 = p0 & 31;
        float4 v0 = make_float4(st[0][c], st[1][c], st[2][c], st[3][c]);
        float4 v1 = make_float4(st[4][c], st[5][c], st[6][c], st[7][c]);
        size_t ob = (((size_t)(b * CH + c) * 64 + hB) * 128 + w0);
        *(float4*)(out + ob)     = v0;
        *(float4*)(out + ob + 4) = v1;
    }
}

// ---------------------------------------------------------------------
extern "C" void kernel_launch(void* const* d_in, const int* in_sizes, int n_in,
                              void* d_out, int out_size) {
    const float* x  = (const float*)d_in[0];
    const float* l  = (const float*)d_in[1];
    const float* w1 = (const float*)d_in[2];
    const float* b1 = (const float*)d_in[3];
    const float* w2 = (const float*)d_in[4];
    const float* b2 = (const float*)d_in[5];
    float* out  = (float*)d_out;
    float* outw = out + POOLED_ELEMS;

    cudaStream_t sB;
    cudaStreamCreateWithFlags(&sB, cudaStreamNonBlocking);
    cudaEvent_t e0, t1, t2, t3, eS, eB;
    cudaEventCreateWithFlags(&e0, cudaEventDisableTiming);
    cudaEventCreateWithFlags(&t1, cudaEventDisableTiming);
    cudaEventCreateWithFlags(&t2, cudaEventDisableTiming);
    cudaEventCreateWithFlags(&t3, cudaEventDisableTiming);
    cudaEventCreateWithFlags(&eS, cudaEventDisableTiming);
    cudaEventCreateWithFlags(&eB, cudaEventDisableTiming);

    // fork point
    cudaEventRecord(e0, 0);

    // main: 4-stage transpose pipeline (2 batches per stage)
    k_T<<<2 * NTPB, 256>>>(x, 0);
    cudaEventRecord(t1, 0);
    k_T<<<2 * NTPB, 256>>>(x, 2);
    cudaEventRecord(t2, 0);
    k_T<<<2 * NTPB, 256>>>(x, 4);
    cudaEventRecord(t3, 0);
    k_T<<<2 * NTPB, 256>>>(x, 6);

    // side: small + fill under stage 0; then red+gather per finished stage
    cudaStreamWaitEvent(sB, e0, 0);
    k_small<<<1, 256, 0, sB>>>(x, l);
    cudaEventRecord(eS, sB);
    k_fill<<<POOLED_ELEMS / 4 / 256, 256, 0, sB>>>(out);
    cudaStreamWaitEvent(sB, t1, 0);
    k_red<<<2, 1024, 0, sB>>>(w1, b1, w2, b2, outw, 0);
    k_g<<<128, 256, 0, sB>>>(l, out, 0);
    cudaStreamWaitEvent(sB, t2, 0);
    k_red<<<2, 1024, 0, sB>>>(w1, b1, w2, b2, outw, 2);
    k_g<<<128, 256, 0, sB>>>(l, out, 2);
    cudaStreamWaitEvent(sB, t3, 0);
    k_red<<<2, 1024, 0, sB>>>(w1, b1, w2, b2, outw, 4);
    k_g<<<128, 256, 0, sB>>>(l, out, 4);
    cudaEventRecord(eB, sB);

    // main: last stage's red + gather
    k_red<<<2, 1024>>>(w1, b1, w2, b2, outw, 6);
    cudaStreamWaitEvent(0, eS, 0);      // polar table ready
    k_g<<<128, 256>>>(l, out, 6);

    // join
    cudaStreamWaitEvent(0, eB, 0);
}

// round 12
// speedup vs baseline: 1.2802x; 1.2802x over previous
#include <cuda_runtime.h>
#include <cuda_fp16.h>
#include <math.h>

#define BATCH 8
#define CH 64
#define PLANE 50176            /* 224*224 */
#define NTPB 1568              /* 32px tiles per batch */
#define NTILES (BATCH*NTPB)    /* 12544 */
#define POOLED_ELEMS 4194304
#define NB_INNER 512
#define NB_FILL 4096

// ---------------- device scratch ----------------
__device__ __half g_xTh[(size_t)BATCH*PLANE*CH];  // [B][pix][C] fp16
__device__ float  g_part[(size_t)NTILES*CH];      // per-tile channel partials
__device__ float  g_lohi[16];
__device__ float  g_cval[BATCH*CH];
__device__ float2 g_polar[8192];                  // (logr, a/pi - 1)
__device__ int    g_done[BATCH];                  // per-batch tile counters

// ---- K1: transpose + partials; per-batch last block does red+MLP -------
__global__ void __launch_bounds__(256) k_T(
        const float* __restrict__ x, const float* __restrict__ l,
        const float* __restrict__ w1, const float* __restrict__ b1,
        const float* __restrict__ w2, const float* __restrict__ b2,
        float* __restrict__ outw) {
    __shared__ float tile[CH][33];
    __shared__ int isLast;
    int bx   = blockIdx.x;
    int b    = bx / NTPB;
    int tidx = bx - b * NTPB;
    int t0   = tidx * 32;
    int tid  = threadIdx.x;

    // ---- transpose one 64ch x 32px tile ----
    const float4* xp = (const float4*)(x + (size_t)b * CH * PLANE);
    int base4 = t0 >> 2;
#pragma unroll
    for (int it = 0; it < 2; it++) {
        int p    = it * 256 + tid;
        int c    = p >> 3;
        int col4 = p & 7;
        float4 v = xp[(size_t)c * (PLANE / 4) + base4 + col4];
        tile[c][col4*4+0] = v.x; tile[c][col4*4+1] = v.y;
        tile[c][col4*4+2] = v.z; tile[c][col4*4+3] = v.w;
    }
    __syncthreads();

    if (tid < CH) {
        float s = 0.f;
#pragma unroll
        for (int k = 0; k < 32; k++) s += tile[tid][k];
        g_part[((size_t)b * NTPB + tidx) * CH + tid] = s;
    }

    {
        int rr = tid >> 3, q = tid & 7;
        half2 h0 = __floats2half2_rn(tile[8*q+0][rr], tile[8*q+1][rr]);
        half2 h1 = __floats2half2_rn(tile[8*q+2][rr], tile[8*q+3][rr]);
        half2 h2 = __floats2half2_rn(tile[8*q+4][rr], tile[8*q+5][rr]);
        half2 h3 = __floats2half2_rn(tile[8*q+6][rr], tile[8*q+7][rr]);
        uint4 u;
        u.x = *(unsigned int*)&h0; u.y = *(unsigned int*)&h1;
        u.z = *(unsigned int*)&h2; u.w = *(unsigned int*)&h3;
        ((uint4*)g_xTh)[((size_t)b * PLANE + t0 + rr) * 8 + q] = u;
    }

    // ---- block 0: polar table (data-independent) ----
    if (bx == 0) {
        for (int e = tid; e < 8192; e += 256) {
            int i = e >> 7, j = e & 127;
            float xg = (i - 32) * (1.f / 32.f);
            float yg = (j - 64) * (1.f / 64.f);
            float logr = logf(fmaxf(sqrtf(xg*xg + yg*yg), 1e-12f));
            float a = atan2f(yg, xg);
            if (!(a > 0.f)) a += 6.283185307179586f;
            g_polar[e] = make_float2(logr, a * 0.3183098861837907f - 1.f);
        }
    }

    // ---- per-batch fan-in: last tile block of batch b reduces ----
    __threadfence();
    __syncthreads();
    if (tid == 0) {
        int old = atomicAdd(&g_done[b], 1);
        isLast = (old == NTPB - 1);
    }
    __syncthreads();
    if (!isLast) return;
    __threadfence();

    __shared__ float4 red4[16][17];
    __shared__ float br[CH];
    __shared__ float hid[32];
    __shared__ float wgt[2];

    {   // reduce 1568 x 16 float4 partials: 16 groups x 98 tiles
        int c4 = tid & 15, grp = tid >> 4;
        const float4* p4 = (const float4*)g_part;
        size_t base = ((size_t)b * NTPB + grp * 98) * 16 + c4;
        float4 a = make_float4(0.f, 0.f, 0.f, 0.f);
#pragma unroll
        for (int t = 0; t < 98; t++) {
            float4 v = __ldg(&p4[base + (size_t)t * 16]);
            a.x += v.x; a.y += v.y; a.z += v.z; a.w += v.w;
        }
        red4[grp][c4] = a;
    }
    __syncthreads();
    if (tid < 16) {
        float4 s = make_float4(0.f, 0.f, 0.f, 0.f);
#pragma unroll
        for (int g = 0; g < 16; g++) {
            float4 v = red4[g][tid];
            s.x += v.x; s.y += v.y; s.z += v.z; s.w += v.w;
        }
        const float inv = 1.f / (float)PLANE;
        br[4*tid+0] = s.x * inv; br[4*tid+1] = s.y * inv;
        br[4*tid+2] = s.z * inv; br[4*tid+3] = s.w * inv;
    }
    __syncthreads();

    if (tid < 32) {
        float acc = b1[tid];
#pragma unroll
        for (int cc = 0; cc < 64; cc++) acc += br[cc] * w1[cc * 32 + tid];
        hid[tid] = fmaxf(acc, 0.f);
    }
    __syncthreads();
    if (tid < 2) {
        float acc = b2[tid];
#pragma unroll
        for (int m = 0; m < 32; m++) acc += hid[m] * w2[m * 2 + tid];
        float wv = 1.f / (1.f + expf(-acc));
        wgt[tid] = wv;
        outw[2 * b + tid] = wv;
    }
    __syncthreads();
    if (tid == 0) {
        g_lohi[2*b + 0] = logf(wgt[0] * 0.01f);
        g_lohi[2*b + 1] = logf(wgt[1] * 0.60f);
        g_done[b] = 0;              // reset for graph replay
    }

    // constant-region bilinear values for this batch (64 channels)
    if (tid < 64) {
        float gx = l[2*b], gy = l[2*b + 1];
        float ix = fminf(fmaxf((gx + 1.f) * 112.f - 0.5f, 0.f), 223.f);
        float iy = fminf(fmaxf((gy + 1.f) * 112.f - 0.5f, 0.f), 223.f);
        float x0f = floorf(ix), y0f = floorf(iy);
        float wx = ix - x0f, wy = iy - y0f;
        int x0 = (int)x0f, y0 = (int)y0f;
        int x1 = min(x0 + 1, 223), y1 = min(y0 + 1, 223);
        const float* pp = x + (size_t)(b * CH + tid) * PLANE;
        g_cval[b * CH + tid] =
              pp[y0*224 + x0] * (1.f-wx) * (1.f-wy)
            + pp[y0*224 + x1] * wx * (1.f-wy)
            + pp[y1*224 + x0] * (1.f-wx) * wy
            + pp[y1*224 + x1] * wx * wy;
    }
}

// ---- K2: fused fill + channel-packed gather + 4x4 pool -----------------
__global__ void __launch_bounds__(256) k_fused(const float* __restrict__ l,
                                               float* __restrict__ out) {
    if (blockIdx.x >= NB_INNER) {
        int idx = (blockIdx.x - NB_INNER) * 256 + threadIdx.x;  // float4 index
        int plane = idx >> 11;
        int rem = idx & 2047;
        int h = rem >> 5, w4 = rem & 31;
        if (h < 16 && w4 < 8) return;
        float v = g_cval[plane];
        __stcs(&((float4*)out)[idx], make_float4(v, v, v, v));
        return;
    }

    __shared__ float st[8][68];
    int warpId = threadIdx.x >> 5;
    int lane   = threadIdx.x & 31;
    int wpos   = blockIdx.x * 8 + warpId;
    int b   = wpos >> 9;
    int pos = wpos & 511;
    int h = pos >> 5, w = pos & 31;
    int tap = lane >> 3, c8 = lane & 7;

    float l0 = l[2*b], l1 = l[2*b + 1];
    float lo = g_lohi[2*b], hi = g_lohi[2*b + 1];
    float inv2 = 2.f / (hi - lo);

    int s16 = lane & 15;
    int i = 4 * h + (s16 >> 2);
    int j = 4 * w + (s16 & 3);
    float2 pb = g_polar[(i << 7) | j];
    float gx = pb.y + l0;
    float gy = (pb.x - lo) * inv2 - 1.f + l1;
    float ix = fminf(fmaxf((gx + 1.f) * 112.f - 0.5f, 0.f), 223.f);
    float iy = fminf(fmaxf((gy + 1.f) * 112.f - 0.5f, 0.f), 223.f);

    const uint4* xt = (const uint4*)g_xTh;
    size_t bbase = (size_t)b * PLANE * 8;
    float acc[8];
#pragma unroll
    for (int k = 0; k < 8; k++) acc[k] = 0.f;

#pragma unroll
    for (int s = 0; s < 16; s++) {
        float ixs = __shfl_sync(0xffffffffu, ix, s);
        float iys = __shfl_sync(0xffffffffu, iy, s);
        float x0f = floorf(ixs), y0f = floorf(iys);
        float wx = ixs - x0f, wy = iys - y0f;
        int x0 = (int)x0f, y0 = (int)y0f;
        int x1 = min(x0 + 1, 223), y1 = min(y0 + 1, 223);
        int xs = (tap & 1) ? x1 : x0;
        int ys = (tap & 2) ? y1 : y0;
        float wt = ((tap & 1) ? wx : 1.f - wx) * ((tap & 2) ? wy : 1.f - wy);
        uint4 v = xt[bbase + (size_t)(ys * 224 + xs) * 8 + c8];
        half2* hp = (half2*)&v;
        float2 f0 = __half22float2(hp[0]);
        float2 f1 = __half22float2(hp[1]);
        float2 f2 = __half22float2(hp[2]);
        float2 f3 = __half22float2(hp[3]);
        acc[0] += wt * f0.x;  acc[1] += wt * f0.y;
        acc[2] += wt * f1.x;  acc[3] += wt * f1.y;
        acc[4] += wt * f2.x;  acc[5] += wt * f2.y;
        acc[6] += wt * f3.x;  acc[7] += wt * f3.y;
    }
#pragma unroll
    for (int k = 0; k < 8; k++) {
        acc[k] += __shfl_xor_sync(0xffffffffu, acc[k], 8);
        acc[k] += __shfl_xor_sync(0xffffffffu, acc[k], 16);
    }
    if (tap == 0) {
#pragma unroll
        for (int k = 0; k < 8; k++)
            st[warpId][8 * c8 + k] = acc[k] * (1.f / 16.f);
    }
    __syncthreads();

    if (threadIdx.x < 64) {
        int c = threadIdx.x;
        int bpos = blockIdx.x * 8;
        int bB = bpos >> 9;
        int p0 = bpos & 511;
        int hB = p0 >> 5, w0 = p0 & 31;
        float4 v0 = make_float4(st[0][c], st[1][c], st[2][c], st[3][c]);
        float4 v1 = make_float4(st[4][c], st[5][c], st[6][c], st[7][c]);
        size_t ob = (((size_t)(bB * CH + c) * 64 + hB) * 128 + w0);
        *(float4*)(out + ob)     = v0;
        *(float4*)(out + ob + 4) = v1;
    }
}

// ---------------------------------------------------------------------
extern "C" void kernel_launch(void* const* d_in, const int* in_sizes, int n_in,
                              void* d_out, int out_size) {
    const float* x  = (const float*)d_in[0];
    const float* l  = (const float*)d_in[1];
    const float* w1 = (const float*)d_in[2];
    const float* b1 = (const float*)d_in[3];
    const float* w2 = (const float*)d_in[4];
    const float* b2 = (const float*)d_in[5];
    float* out  = (float*)d_out;
    float* outw = out + POOLED_ELEMS;

    k_T<<<NTILES, 256>>>(x, l, w1, b1, w2, b2, outw);
    k_fused<<<NB_INNER + NB_FILL, 256>>>(l, out);
}

// round 13
// speedup vs baseline: 1.4347x; 1.1207x over previous
#include <cuda_runtime.h>
#include <cuda_fp16.h>
#include <math.h>

#define BATCH 8
#define CH 64
#define PLANE 50176            /* 224*224 */
#define NTPB 1568              /* 32px tiles per batch */
#define NTILES (BATCH*NTPB)    /* 12544 */
#define POOLED_ELEMS 4194304
#define NB_INNER 512
#define NB_FILL 4096

// ---------------- device scratch ----------------
__device__ __half g_xTh[(size_t)BATCH*PLANE*CH];  // [B][pix][C] fp16
__device__ float  g_part[(size_t)NTILES*CH];      // per-tile channel partials
__device__ float  g_lohi[16];
__device__ float  g_cval[BATCH*CH];
__device__ float2 g_polar[8192];                  // (logr, a/pi - 1)

// ---- K1: pure transpose + per-tile partials (+polar in block 0) --------
__global__ void __launch_bounds__(256) k_T(const float* __restrict__ x) {
    __shared__ float tile[CH][33];
    int bx   = blockIdx.x;
    int b    = bx / NTPB;
    int tidx = bx - b * NTPB;
    int t0   = tidx * 32;
    int tid  = threadIdx.x;

    const float4* xp = (const float4*)(x + (size_t)b * CH * PLANE);
    int base4 = t0 >> 2;
#pragma unroll
    for (int it = 0; it < 2; it++) {
        int p    = it * 256 + tid;
        int c    = p >> 3;
        int col4 = p & 7;
        float4 v = xp[(size_t)c * (PLANE / 4) + base4 + col4];
        tile[c][col4*4+0] = v.x; tile[c][col4*4+1] = v.y;
        tile[c][col4*4+2] = v.z; tile[c][col4*4+3] = v.w;
    }
    __syncthreads();

    if (tid < CH) {
        float s = 0.f;
#pragma unroll
        for (int k = 0; k < 32; k++) s += tile[tid][k];
        g_part[((size_t)b * NTPB + tidx) * CH + tid] = s;
    }

    int rr = tid >> 3, q = tid & 7;
    half2 h0 = __floats2half2_rn(tile[8*q+0][rr], tile[8*q+1][rr]);
    half2 h1 = __floats2half2_rn(tile[8*q+2][rr], tile[8*q+3][rr]);
    half2 h2 = __floats2half2_rn(tile[8*q+4][rr], tile[8*q+5][rr]);
    half2 h3 = __floats2half2_rn(tile[8*q+6][rr], tile[8*q+7][rr]);
    uint4 u;
    u.x = *(unsigned int*)&h0; u.y = *(unsigned int*)&h1;
    u.z = *(unsigned int*)&h2; u.w = *(unsigned int*)&h3;
    ((uint4*)g_xTh)[((size_t)b * PLANE + t0 + rr) * 8 + q] = u;

    if (bx == 0) {   // polar table (data-independent, plain stores)
        for (int e = tid; e < 8192; e += 256) {
            int i = e >> 7, j = e & 127;
            float xg = (i - 32) * (1.f / 32.f);
            float yg = (j - 64) * (1.f / 64.f);
            float logr = logf(fmaxf(sqrtf(xg*xg + yg*yg), 1e-12f));
            float a = atan2f(yg, xg);
            if (!(a > 0.f)) a += 6.283185307179586f;
            g_polar[e] = make_float2(logr, a * 0.3183098861837907f - 1.f);
        }
    }
}

// ---- K2: per-batch reduce + MLP + lo/hi + cval (8 blocks) ---------------
__global__ void __launch_bounds__(256) k_red(
        const float* __restrict__ x, const float* __restrict__ l,
        const float* __restrict__ w1, const float* __restrict__ b1,
        const float* __restrict__ w2, const float* __restrict__ b2,
        float* __restrict__ outw) {
    __shared__ float4 red4[16][17];
    __shared__ float br[CH];
    __shared__ float hid[32];
    __shared__ float wgt[2];
    int b = blockIdx.x;
    int tid = threadIdx.x;

    {   // reduce 1568 tiles x 16 float4: 16 groups x 98 tiles, unrolled
        int c4 = tid & 15, grp = tid >> 4;
        const float4* p4 = (const float4*)g_part;
        size_t base = ((size_t)b * NTPB + grp * 98) * 16 + c4;
        float4 a = make_float4(0.f, 0.f, 0.f, 0.f);
#pragma unroll
        for (int t = 0; t < 98; t++) {
            float4 v = __ldg(&p4[base + (size_t)t * 16]);
            a.x += v.x; a.y += v.y; a.z += v.z; a.w += v.w;
        }
        red4[grp][c4] = a;
    }
    __syncthreads();
    if (tid < 16) {
        float4 s = make_float4(0.f, 0.f, 0.f, 0.f);
#pragma unroll
        for (int g = 0; g < 16; g++) {
            float4 v = red4[g][tid];
            s.x += v.x; s.y += v.y; s.z += v.z; s.w += v.w;
        }
        const float inv = 1.f / (float)PLANE;
        br[4*tid+0] = s.x * inv; br[4*tid+1] = s.y * inv;
        br[4*tid+2] = s.z * inv; br[4*tid+3] = s.w * inv;
    }
    __syncthreads();

    if (tid < 32) {
        float acc = b1[tid];
#pragma unroll
        for (int cc = 0; cc < 64; cc++) acc += br[cc] * w1[cc * 32 + tid];
        hid[tid] = fmaxf(acc, 0.f);
    }
    __syncthreads();
    if (tid < 2) {
        float acc = b2[tid];
#pragma unroll
        for (int m = 0; m < 32; m++) acc += hid[m] * w2[m * 2 + tid];
        float wv = 1.f / (1.f + expf(-acc));
        wgt[tid] = wv;
        outw[2 * b + tid] = wv;
    }
    __syncthreads();
    if (tid == 0) {
        g_lohi[2*b + 0] = logf(wgt[0] * 0.01f);
        g_lohi[2*b + 1] = logf(wgt[1] * 0.60f);
    }

    if (tid < 64) {   // constant-region bilinear value per channel
        float gx = l[2*b], gy = l[2*b + 1];
        float ix = fminf(fmaxf((gx + 1.f) * 112.f - 0.5f, 0.f), 223.f);
        float iy = fminf(fmaxf((gy + 1.f) * 112.f - 0.5f, 0.f), 223.f);
        float x0f = floorf(ix), y0f = floorf(iy);
        float wx = ix - x0f, wy = iy - y0f;
        int x0 = (int)x0f, y0 = (int)y0f;
        int x1 = min(x0 + 1, 223), y1 = min(y0 + 1, 223);
        const float* pp = x + (size_t)(b * CH + tid) * PLANE;
        g_cval[b * CH + tid] =
              pp[y0*224 + x0] * (1.f-wx) * (1.f-wy)
            + pp[y0*224 + x1] * wx * (1.f-wy)
            + pp[y1*224 + x0] * (1.f-wx) * wy
            + pp[y1*224 + x1] * wx * wy;
    }
}

// ---- K3: fused fill + channel-packed gather + 4x4 pool -----------------
__global__ void __launch_bounds__(256) k_fused(const float* __restrict__ l,
                                               float* __restrict__ out) {
    if (blockIdx.x >= NB_INNER) {
        int idx = (blockIdx.x - NB_INNER) * 256 + threadIdx.x;  // float4 index
        int plane = idx >> 11;
        int rem = idx & 2047;
        int h = rem >> 5, w4 = rem & 31;
        if (h < 16 && w4 < 8) return;
        float v = g_cval[plane];
        __stcs(&((float4*)out)[idx], make_float4(v, v, v, v));
        return;
    }

    __shared__ float st[8][68];
    int warpId = threadIdx.x >> 5;
    int lane   = threadIdx.x & 31;
    int wpos   = blockIdx.x * 8 + warpId;
    int b   = wpos >> 9;
    int pos = wpos & 511;
    int h = pos >> 5, w = pos & 31;
    int tap = lane >> 3, c8 = lane & 7;

    float l0 = l[2*b], l1 = l[2*b + 1];
    float lo = g_lohi[2*b], hi = g_lohi[2*b + 1];
    float inv2 = 2.f / (hi - lo);

    int s16 = lane & 15;
    int i = 4 * h + (s16 >> 2);
    int j = 4 * w + (s16 & 3);
    float2 pb = g_polar[(i << 7) | j];
    float gx = pb.y + l0;
    float gy = (pb.x - lo) * inv2 - 1.f + l1;
    float ix = fminf(fmaxf((gx + 1.f) * 112.f - 0.5f, 0.f), 223.f);
    float iy = fminf(fmaxf((gy + 1.f) * 112.f - 0.5f, 0.f), 223.f);

    const uint4* xt = (const uint4*)g_xTh;
    size_t bbase = (size_t)b * PLANE * 8;
    float acc[8];
#pragma unroll
    for (int k = 0; k < 8; k++) acc[k] = 0.f;

#pragma unroll
    for (int s = 0; s < 16; s++) {
        float ixs = __shfl_sync(0xffffffffu, ix, s);
        float iys = __shfl_sync(0xffffffffu, iy, s);
        float x0f = floorf(ixs), y0f = floorf(iys);
        float wx = ixs - x0f, wy = iys - y0f;
        int x0 = (int)x0f, y0 = (int)y0f;
        int x1 = min(x0 + 1, 223), y1 = min(y0 + 1, 223);
        int xs = (tap & 1) ? x1 : x0;
        int ys = (tap & 2) ? y1 : y0;
        float wt = ((tap & 1) ? wx : 1.f - wx) * ((tap & 2) ? wy : 1.f - wy);
        uint4 v = xt[bbase + (size_t)(ys * 224 + xs) * 8 + c8];
        half2* hp = (half2*)&v;
        float2 f0 = __half22float2(hp[0]);
        float2 f1 = __half22float2(hp[1]);
        float2 f2 = __half22float2(hp[2]);
        float2 f3 = __half22float2(hp[3]);
        acc[0] += wt * f0.x;  acc[1] += wt * f0.y;
        acc[2] += wt * f1.x;  acc[3] += wt * f1.y;
        acc[4] += wt * f2.x;  acc[5] += wt * f2.y;
        acc[6] += wt * f3.x;  acc[7] += wt * f3.y;
    }
#pragma unroll
    for (int k = 0; k < 8; k++) {
        acc[k] += __shfl_xor_sync(0xffffffffu, acc[k], 8);
        acc[k] += __shfl_xor_sync(0xffffffffu, acc[k], 16);
    }
    if (tap == 0) {
#pragma unroll
        for (int k = 0; k < 8; k++)
            st[warpId][8 * c8 + k] = acc[k] * (1.f / 16.f);
    }
    __syncthreads();

    if (threadIdx.x < 64) {
        int c = threadIdx.x;
        int bpos = blockIdx.x * 8;
        int bB = bpos >> 9;
        int p0 = bpos & 511;
        int hB = p0 >> 5, w0 = p0 & 31;
        float4 v0 = make_float4(st[0][c], st[1][c], st[2][c], st[3][c]);
        float4 v1 = make_float4(st[4][c], st[5][c], st[6][c], st[7][c]);
        size_t ob = (((size_t)(bB * CH + c) * 64 + hB) * 128 + w0);
        *(float4*)(out + ob)     = v0;
        *(float4*)(out + ob + 4) = v1;
    }
}

// ---------------------------------------------------------------------
extern "C" void kernel_launch(void* const* d_in, const int* in_sizes, int n_in,
                              void* d_out, int out_size) {
    const float* x  = (const float*)d_in[0];
    const float* l  = (const float*)d_in[1];
    const float* w1 = (const float*)d_in[2];
    const float* b1 = (const float*)d_in[3];
    const float* w2 = (const float*)d_in[4];
    const float* b2 = (const float*)d_in[5];
    float* out  = (float*)d_out;
    float* outw = out + POOLED_ELEMS;

    k_T<<<NTILES, 256>>>(x);
    k_red<<<BATCH, 256>>>(x, l, w1, b1, w2, b2, outw);
    k_fused<<<NB_INNER + NB_FILL, 256>>>(l, out);
}

// round 14
// speedup vs baseline: 1.6606x; 1.1574x over previous
#include <cuda_runtime.h>
#include <cuda_fp16.h>
#include <math.h>

#define BATCH 8
#define CH 64
#define PLANE 50176            /* 224*224 */
#define NTPB 1568              /* 32px tiles per batch */
#define NTILES (BATCH*NTPB)    /* 12544 */
#define POOLED_ELEMS 4194304
#define NB_INNER 512
#define NB_FILL 4096

// ---------------- device scratch ----------------
__device__ __half g_xTh[(size_t)BATCH*PLANE*CH];  // [B][pix][C] fp16
__device__ float  g_part[(size_t)NTILES*CH];      // per-tile channel partials
__device__ float  g_lohi[16];
__device__ float  g_cval[BATCH*CH];
__device__ float2 g_polar[8192];                  // (logr, a/pi - 1)

// ---- K1: transpose + partials; block0 polar, block1 cval ----------------
__global__ void __launch_bounds__(256) k_T(const float* __restrict__ x,
                                           const float* __restrict__ l) {
    __shared__ float tile[CH][33];
    int bx   = blockIdx.x;
    int b    = bx / NTPB;
    int tidx = bx - b * NTPB;
    int t0   = tidx * 32;
    int tid  = threadIdx.x;

    const float4* xp = (const float4*)(x + (size_t)b * CH * PLANE);
    int base4 = t0 >> 2;
#pragma unroll
    for (int it = 0; it < 2; it++) {
        int p    = it * 256 + tid;
        int c    = p >> 3;
        int col4 = p & 7;
        float4 v = xp[(size_t)c * (PLANE / 4) + base4 + col4];
        tile[c][col4*4+0] = v.x; tile[c][col4*4+1] = v.y;
        tile[c][col4*4+2] = v.z; tile[c][col4*4+3] = v.w;
    }
    __syncthreads();

    if (tid < CH) {
        float s = 0.f;
#pragma unroll
        for (int k = 0; k < 32; k++) s += tile[tid][k];
        g_part[((size_t)b * NTPB + tidx) * CH + tid] = s;
    }

    int rr = tid >> 3, q = tid & 7;
    half2 h0 = __floats2half2_rn(tile[8*q+0][rr], tile[8*q+1][rr]);
    half2 h1 = __floats2half2_rn(tile[8*q+2][rr], tile[8*q+3][rr]);
    half2 h2 = __floats2half2_rn(tile[8*q+4][rr], tile[8*q+5][rr]);
    half2 h3 = __floats2half2_rn(tile[8*q+6][rr], tile[8*q+7][rr]);
    uint4 u;
    u.x = *(unsigned int*)&h0; u.y = *(unsigned int*)&h1;
    u.z = *(unsigned int*)&h2; u.w = *(unsigned int*)&h3;
    ((uint4*)g_xTh)[((size_t)b * PLANE + t0 + rr) * 8 + q] = u;

    if (bx == 0) {       // polar table (data-independent, plain stores)
        for (int e = tid; e < 8192; e += 256) {
            int i = e >> 7, j = e & 127;
            float xg = (i - 32) * (1.f / 32.f);
            float yg = (j - 64) * (1.f / 64.f);
            float logr = logf(fmaxf(sqrtf(xg*xg + yg*yg), 1e-12f));
            float a = atan2f(yg, xg);
            if (!(a > 0.f)) a += 6.283185307179586f;
            g_polar[e] = make_float2(logr, a * 0.3183098861837907f - 1.f);
        }
    } else if (bx == 1) {   // constant-region bilinear values (x + l only)
#pragma unroll
        for (int rep = 0; rep < 2; rep++) {
            int idx = rep * 256 + tid;      // (bb, c)
            int bb = idx >> 6;
            float gx = l[2*bb], gy = l[2*bb + 1];
            float ix = fminf(fmaxf((gx + 1.f) * 112.f - 0.5f, 0.f), 223.f);
            float iy = fminf(fmaxf((gy + 1.f) * 112.f - 0.5f, 0.f), 223.f);
            float x0f = floorf(ix), y0f = floorf(iy);
            float wx = ix - x0f, wy = iy - y0f;
            int x0 = (int)x0f, y0 = (int)y0f;
            int x1 = min(x0 + 1, 223), y1 = min(y0 + 1, 223);
            const float* pp = x + (size_t)idx * PLANE;
            g_cval[idx] = pp[y0*224 + x0] * (1.f-wx) * (1.f-wy)
                        + pp[y0*224 + x1] * wx * (1.f-wy)
                        + pp[y1*224 + x0] * (1.f-wx) * wy
                        + pp[y1*224 + x1] * wx * wy;
        }
    }
}

// ---- K2: per-batch reduce + MLP + lo/hi only (8 blocks x 512) -----------
__global__ void __launch_bounds__(512) k_red(
        const float* __restrict__ w1, const float* __restrict__ b1,
        const float* __restrict__ w2, const float* __restrict__ b2,
        float* __restrict__ outw) {
    __shared__ float4 red4[32][16];
    __shared__ float br[CH];
    __shared__ float hid[32];
    __shared__ float wgt[2];
    int b = blockIdx.x;
    int tid = threadIdx.x;

    {   // 32 groups x 49 tiles, fully unrolled float4 accumulate
        int c4 = tid & 15, grp = tid >> 4;    // grp 0..31
        const float4* p4 = (const float4*)g_part;
        size_t base = ((size_t)b * NTPB + grp * 49) * 16 + c4;
        float4 a = make_float4(0.f, 0.f, 0.f, 0.f);
#pragma unroll
        for (int t = 0; t < 49; t++) {
            float4 v = p4[base + (size_t)t * 16];
            a.x += v.x; a.y += v.y; a.z += v.z; a.w += v.w;
        }
        red4[grp][c4] = a;
    }
    __syncthreads();
    if (tid < 16) {
        float4 s = make_float4(0.f, 0.f, 0.f, 0.f);
#pragma unroll
        for (int g = 0; g < 32; g++) {
            float4 v = red4[g][tid];
            s.x += v.x; s.y += v.y; s.z += v.z; s.w += v.w;
        }
        const float inv = 1.f / (float)PLANE;
        br[4*tid+0] = s.x * inv; br[4*tid+1] = s.y * inv;
        br[4*tid+2] = s.z * inv; br[4*tid+3] = s.w * inv;
    }
    __syncthreads();

    if (tid < 32) {
        float acc = b1[tid];
#pragma unroll
        for (int cc = 0; cc < 64; cc++) acc += br[cc] * w1[cc * 32 + tid];
        hid[tid] = fmaxf(acc, 0.f);
    }
    __syncthreads();
    if (tid < 2) {
        float acc = b2[tid];
#pragma unroll
        for (int m = 0; m < 32; m++) acc += hid[m] * w2[m * 2 + tid];
        float wv = 1.f / (1.f + expf(-acc));
        wgt[tid] = wv;
        outw[2 * b + tid] = wv;
    }
    __syncthreads();
    if (tid == 0) {
        g_lohi[2*b + 0] = logf(wgt[0] * 0.01f);
        g_lohi[2*b + 1] = logf(wgt[1] * 0.60f);
    }
}

// ---- K3: fused fill + channel-packed gather + 4x4 pool -----------------
__global__ void __launch_bounds__(256) k_fused(const float* __restrict__ l,
                                               float* __restrict__ out) {
    if (blockIdx.x >= NB_INNER) {
        int idx = (blockIdx.x - NB_INNER) * 256 + threadIdx.x;  // float4 index
        int plane = idx >> 11;
        int rem = idx & 2047;
        int h = rem >> 5, w4 = rem & 31;
        if (h < 16 && w4 < 8) return;
        float v = g_cval[plane];
        __stcs(&((float4*)out)[idx], make_float4(v, v, v, v));
        return;
    }

    __shared__ float st[8][68];
    int warpId = threadIdx.x >> 5;
    int lane   = threadIdx.x & 31;
    int wpos   = blockIdx.x * 8 + warpId;
    int b   = wpos >> 9;
    int pos = wpos & 511;
    int h = pos >> 5, w = pos & 31;
    int tap = lane >> 3, c8 = lane & 7;

    float l0 = l[2*b], l1 = l[2*b + 1];
    float lo = g_lohi[2*b], hi = g_lohi[2*b + 1];
    float inv2 = 2.f / (hi - lo);

    int s16 = lane & 15;
    int i = 4 * h + (s16 >> 2);
    int j = 4 * w + (s16 & 3);
    float2 pb = g_polar[(i << 7) | j];
    float gx = pb.y + l0;
    float gy = (pb.x - lo) * inv2 - 1.f + l1;
    float ix = fminf(fmaxf((gx + 1.f) * 112.f - 0.5f, 0.f), 223.f);
    float iy = fminf(fmaxf((gy + 1.f) * 112.f - 0.5f, 0.f), 223.f);

    const uint4* xt = (const uint4*)g_xTh;
    size_t bbase = (size_t)b * PLANE * 8;
    float acc[8];
#pragma unroll
    for (int k = 0; k < 8; k++) acc[k] = 0.f;

#pragma unroll
    for (int s = 0; s < 16; s++) {
        float ixs = __shfl_sync(0xffffffffu, ix, s);
        float iys = __shfl_sync(0xffffffffu, iy, s);
        float x0f = floorf(ixs), y0f = floorf(iys);
        float wx = ixs - x0f, wy = iys - y0f;
        int x0 = (int)x0f, y0 = (int)y0f;
        int x1 = min(x0 + 1, 223), y1 = min(y0 + 1, 223);
        int xs = (tap & 1) ? x1 : x0;
        int ys = (tap & 2) ? y1 : y0;
        float wt = ((tap & 1) ? wx : 1.f - wx) * ((tap & 2) ? wy : 1.f - wy);
        uint4 v = xt[bbase + (size_t)(ys * 224 + xs) * 8 + c8];
        half2* hp = (half2*)&v;
        float2 f0 = __half22float2(hp[0]);
        float2 f1 = __half22float2(hp[1]);
        float2 f2 = __half22float2(hp[2]);
        float2 f3 = __half22float2(hp[3]);
        acc[0] += wt * f0.x;  acc[1] += wt * f0.y;
        acc[2] += wt * f1.x;  acc[3] += wt * f1.y;
        acc[4] += wt * f2.x;  acc[5] += wt * f2.y;
        acc[6] += wt * f3.x;  acc[7] += wt * f3.y;
    }
#pragma unroll
    for (int k = 0; k < 8; k++) {
        acc[k] += __shfl_xor_sync(0xffffffffu, acc[k], 8);
        acc[k] += __shfl_xor_sync(0xffffffffu, acc[k], 16);
    }
    if (tap == 0) {
#pragma unroll
        for (int k = 0; k < 8; k++)
            st[warpId][8 * c8 + k] = acc[k] * (1.f / 16.f);
    }
    __syncthreads();

    if (threadIdx.x < 64) {
        int c = threadIdx.x;
        int bpos = blockIdx.x * 8;
        int bB = bpos >> 9;
        int p0 = bpos & 511;
        int hB = p0 >> 5, w0 = p0 & 31;
        float4 v0 = make_float4(st[0][c], st[1][c], st[2][c], st[3][c]);
        float4 v1 = make_float4(st[4][c], st[5][c], st[6][c], st[7][c]);
        size_t ob = (((size_t)(bB * CH + c) * 64 + hB) * 128 + w0);
        *(float4*)(out + ob)     = v0;
        *(float4*)(out + ob + 4) = v1;
    }
}

// ---------------------------------------------------------------------
extern "C" void kernel_launch(void* const* d_in, const int* in_sizes, int n_in,
                              void* d_out, int out_size) {
    const float* x  = (const float*)d_in[0];
    const float* l  = (const float*)d_in[1];
    const float* w1 = (const float*)d_in[2];
    const float* b1 = (const float*)d_in[3];
    const float* w2 = (const float*)d_in[4];
    const float* b2 = (const float*)d_in[5];
    float* out  = (float*)d_out;
    float* outw = out + POOLED_ELEMS;

    k_T<<<NTILES, 256>>>(x, l);
    k_red<<<BATCH, 512>>>(w1, b1, w2, b2, outw);
    k_fused<<<NB_INNER + NB_FILL, 256>>>(l, out);
}